// round 6
// baseline (speedup 1.0000x reference)
#include <cuda_runtime.h>

#define NEG_SLOPE 0.2f
#define MAXN 100000
#define MAXE 3200000
#define EPT 2          // edges per thread in edge passes

static __device__ __forceinline__ float lrelu(float v) {
    return v > 0.f ? v : NEG_SLOPE * v;
}

static __device__ __forceinline__ void red_add_v2(float* addr, float a, float b) {
    asm volatile("red.global.add.v2.f32 [%0], {%1,%2};" :: "l"(addr), "f"(a), "f"(b) : "memory");
}
static __device__ __forceinline__ void red_add_v4(float* addr, float a, float b, float c, float d) {
    asm volatile("red.global.add.v4.f32 [%0], {%1,%2,%3,%4};"
                 :: "l"(addr), "f"(a), "f"(b), "f"(c), "f"(d) : "memory");
}

static __device__ __forceinline__ float dot3(float4 v, float4 c) {
    return v.x * c.x + v.y * c.y + v.z * c.z;
}

// ---------------- scratch (device globals; no runtime allocation) ----------------
__device__ __align__(16) int2 g_sd[MAXE];    // packed (src,dst): written by edge1, read by edge2

// Layer-1: per-node state is x (float4, 1 sector). Scores are linear in x.
__device__ __align__(16) float4 g_X[MAXN];
__device__ float4 g_csf, g_cdf, g_csr, g_cdr;   // W1@as1, W1@ad1, W1r@as1r, W1r@ad1r
// Accumulators: (sum w*x0, w*x1, w*x2, sum w)
__device__ __align__(16) float4 g_accf[MAXN];
__device__ __align__(16) float4 g_accr[MAXN];

// Layer-2: per-node state is (h2f, h2r).
__device__ __align__(16) float2 g_H[MAXN];
__device__ __align__(16) float2 g_nd2f[MAXN];
__device__ __align__(16) float2 g_nd2r[MAXN];

// ---------------- layer 1 node prep (score coefficients computed per block) ----------------
__global__ void k_node1(const float* __restrict__ x,
                        const float* __restrict__ W1,  const float* __restrict__ as1,
                        const float* __restrict__ ad1,
                        const float* __restrict__ W1r, const float* __restrict__ as1r,
                        const float* __restrict__ ad1r, int N) {
    __shared__ float4 s_c[4];    // csf, cdf, csr, cdr
    if (threadIdx.x == 0) {
        float csf[3] = {0,0,0}, cdf[3] = {0,0,0}, csr[3] = {0,0,0}, cdr[3] = {0,0,0};
#pragma unroll
        for (int f = 0; f < 16; f++) {
            float a1 = __ldg(&as1[f]),  a2 = __ldg(&ad1[f]);
            float a3 = __ldg(&as1r[f]), a4 = __ldg(&ad1r[f]);
#pragma unroll
            for (int k = 0; k < 3; k++) {
                float w  = __ldg(&W1[16 * k + f]);
                float wr = __ldg(&W1r[16 * k + f]);
                csf[k] += w * a1;  cdf[k] += w * a2;
                csr[k] += wr * a3; cdr[k] += wr * a4;
            }
        }
        s_c[0] = make_float4(csf[0], csf[1], csf[2], 0.f);
        s_c[1] = make_float4(cdf[0], cdf[1], cdf[2], 0.f);
        s_c[2] = make_float4(csr[0], csr[1], csr[2], 0.f);
        s_c[3] = make_float4(cdr[0], cdr[1], cdr[2], 0.f);
        if (blockIdx.x == 0) {   // publish uniform coefficients for k_edge1
            g_csf = s_c[0]; g_cdf = s_c[1]; g_csr = s_c[2]; g_cdr = s_c[3];
        }
    }
    __syncthreads();

    int i = blockIdx.x * blockDim.x + threadIdx.x;
    if (i >= N) return;
    float x0 = x[3 * i], x1 = x[3 * i + 1], x2 = x[3 * i + 2];
    float4 X = make_float4(x0, x1, x2, 0.f);

    float ssf = dot3(X, s_c[0]), sdf = dot3(X, s_c[1]);
    float ssr = dot3(X, s_c[2]), sdr = dot3(X, s_c[3]);

    g_X[i] = X;
    // self-loop contribution
    float wf = __expf(lrelu(ssf + sdf));
    float wr = __expf(lrelu(ssr + sdr));
    g_accf[i] = make_float4(wf * x0, wf * x1, wf * x2, wf);
    g_accr[i] = make_float4(wr * x0, wr * x1, wr * x2, wr);
}

// ---------------- layer 1 edge pass: 2 gathers + 2 REDs per edge ----------------
__global__ void __launch_bounds__(256, 6) k_edge1(const void* __restrict__ ei, int E) {
    // per-block int64-vs-int32 detection: odd 32-bit words of int64 data are
    // all-zero high halves; genuine int32 node ids are ~never 128-in-a-row zero.
    __shared__ int s_is64;
    if (threadIdx.x == 0) s_is64 = 1;
    __syncthreads();
    if (threadIdx.x < 128) {
        if (((const int*)ei)[1 + 2 * threadIdx.x] != 0) s_is64 = 0;
    }
    __syncthreads();
    bool is64 = (s_is64 != 0);

    int t = blockIdx.x * blockDim.x + threadIdx.x;
    int j0 = t * EPT;
    if (j0 >= E) return;
    int n = E - j0; if (n > EPT) n = EPT;

    float4 csf = g_csf, cdf = g_cdf, csr = g_csr, cdr = g_cdr;

    int s[EPT], d[EPT];
    if (is64) {
        const long long* p = (const long long*)ei;
#pragma unroll
        for (int u = 0; u < EPT; u++) if (u < n) { s[u] = (int)p[j0 + u]; d[u] = (int)p[E + j0 + u]; }
    } else {
        const int* p = (const int*)ei;
#pragma unroll
        for (int u = 0; u < EPT; u++) if (u < n) { s[u] = p[j0 + u]; d[u] = p[E + j0 + u]; }
    }
#pragma unroll
    for (int u = 0; u < EPT; u++) if (u < n) g_sd[j0 + u] = make_int2(s[u], d[u]);

    float4 Xs[EPT], Xd[EPT];
#pragma unroll
    for (int u = 0; u < EPT; u++) if (u < n) {
        Xs[u] = g_X[s[u]];
        Xd[u] = g_X[d[u]];
    }
#pragma unroll
    for (int u = 0; u < EPT; u++) if (u < n) {
        // forward edge s->d: exp(lrelu(ssf[s] + sdf[d])) -> accf[d]
        float wf = __expf(lrelu(dot3(Xs[u], csf) + dot3(Xd[u], cdf)));
        // reverse edge d->s: exp(lrelu(ssr[d] + sdr[s])) -> accr[s]
        float wr = __expf(lrelu(dot3(Xd[u], csr) + dot3(Xs[u], cdr)));
        red_add_v4((float*)&g_accf[d[u]], wf * Xs[u].x, wf * Xs[u].y, wf * Xs[u].z, wf);
        red_add_v4((float*)&g_accr[s[u]], wr * Xd[u].x, wr * Xd[u].y, wr * Xd[u].z, wr);
    }
}

// ---------------- layer 2 node prep: 2 nodes/thread, shared weight loads ----------------
__global__ void k_node2(const float* __restrict__ W1, const float* __restrict__ b1,
                        const float* __restrict__ W2,
                        const float* __restrict__ as2, const float* __restrict__ ad2,
                        const float* __restrict__ W1r, const float* __restrict__ b1r,
                        const float* __restrict__ W2r,
                        const float* __restrict__ as2r, const float* __restrict__ ad2r, int N) {
    int t = blockIdx.x * blockDim.x + threadIdx.x;
    int i0 = 2 * t;
    if (i0 >= N) return;
    int cnt = (i0 + 1 < N) ? 2 : 1;

    float nf[2][3], nr[2][3];
#pragma unroll
    for (int v = 0; v < 2; v++) if (v < cnt) {
        float4 af = g_accf[i0 + v];
        float4 ar = g_accr[i0 + v];
        float invf = 1.f / (af.w + 1e-16f);
        float invr = 1.f / (ar.w + 1e-16f);
        nf[v][0] = af.x * invf; nf[v][1] = af.y * invf; nf[v][2] = af.z * invf;
        nr[v][0] = ar.x * invr; nr[v][1] = ar.y * invr; nr[v][2] = ar.z * invr;
    }

    const float4* W1v  = (const float4*)W1;   // [3][4] float4s
    const float4* W1rv = (const float4*)W1r;
    const float4* b1v  = (const float4*)b1;
    const float4* b1rv = (const float4*)b1r;
    const float4* W2v  = (const float4*)W2;
    const float4* W2rv = (const float4*)W2r;

    float h2f[2] = {0.f, 0.f}, h2r[2] = {0.f, 0.f};
#pragma unroll
    for (int q = 0; q < 4; q++) {
        float4 w0 = __ldg(&W1v[q]),  w1 = __ldg(&W1v[4 + q]),  w2 = __ldg(&W1v[8 + q]);
        float4 bb = __ldg(&b1v[q]),  wo = __ldg(&W2v[q]);
        float4 r0 = __ldg(&W1rv[q]), r1 = __ldg(&W1rv[4 + q]), r2 = __ldg(&W1rv[8 + q]);
        float4 br = __ldg(&b1rv[q]), ro = __ldg(&W2rv[q]);
#pragma unroll
        for (int v = 0; v < 2; v++) if (v < cnt) {
            h2f[v] += fmaxf(nf[v][0] * w0.x + nf[v][1] * w1.x + nf[v][2] * w2.x + bb.x, 0.f) * wo.x;
            h2f[v] += fmaxf(nf[v][0] * w0.y + nf[v][1] * w1.y + nf[v][2] * w2.y + bb.y, 0.f) * wo.y;
            h2f[v] += fmaxf(nf[v][0] * w0.z + nf[v][1] * w1.z + nf[v][2] * w2.z + bb.z, 0.f) * wo.z;
            h2f[v] += fmaxf(nf[v][0] * w0.w + nf[v][1] * w1.w + nf[v][2] * w2.w + bb.w, 0.f) * wo.w;
            h2r[v] += fmaxf(nr[v][0] * r0.x + nr[v][1] * r1.x + nr[v][2] * r2.x + br.x, 0.f) * ro.x;
            h2r[v] += fmaxf(nr[v][0] * r0.y + nr[v][1] * r1.y + nr[v][2] * r2.y + br.y, 0.f) * ro.y;
            h2r[v] += fmaxf(nr[v][0] * r0.z + nr[v][1] * r1.z + nr[v][2] * r2.z + br.z, 0.f) * ro.z;
            h2r[v] += fmaxf(nr[v][0] * r0.w + nr[v][1] * r1.w + nr[v][2] * r2.w + br.w, 0.f) * ro.w;
        }
    }

    float sum2f = __ldg(&as2[0]) + __ldg(&ad2[0]);
    float sum2r = __ldg(&as2r[0]) + __ldg(&ad2r[0]);
#pragma unroll
    for (int v = 0; v < 2; v++) if (v < cnt) {
        g_H[i0 + v] = make_float2(h2f[v], h2r[v]);
        float wf = __expf(lrelu(h2f[v] * sum2f));
        float wr = __expf(lrelu(h2r[v] * sum2r));
        g_nd2f[i0 + v] = make_float2(wf * h2f[v], wf);
        g_nd2r[i0 + v] = make_float2(wr * h2r[v], wr);
    }
}

// ---------------- layer 2 edge pass: 2 gathers + 2 REDs per edge ----------------
__global__ void __launch_bounds__(256, 6) k_edge2(const float* __restrict__ as2,
                                                  const float* __restrict__ ad2,
                                                  const float* __restrict__ as2r,
                                                  const float* __restrict__ ad2r, int E) {
    float a2s = __ldg(&as2[0]),  a2d = __ldg(&ad2[0]);
    float a2sr = __ldg(&as2r[0]), a2dr = __ldg(&ad2r[0]);

    int t = blockIdx.x * blockDim.x + threadIdx.x;
    int j0 = t * EPT;
    if (j0 >= E) return;
    int n = E - j0; if (n > EPT) n = EPT;

    int2 sd[EPT];
#pragma unroll
    for (int u = 0; u < EPT; u++) if (u < n) sd[u] = g_sd[j0 + u];

    float2 Hs[EPT], Hd[EPT];
#pragma unroll
    for (int u = 0; u < EPT; u++) if (u < n) {
        Hs[u] = g_H[sd[u].x];
        Hd[u] = g_H[sd[u].y];
    }
#pragma unroll
    for (int u = 0; u < EPT; u++) if (u < n) {
        // forward s->d: score = h2f[s]*as2 + h2f[d]*ad2
        float wf = __expf(lrelu(Hs[u].x * a2s + Hd[u].x * a2d));
        // reverse d->s: score = h2r[d]*as2r + h2r[s]*ad2r
        float wr = __expf(lrelu(Hd[u].y * a2sr + Hs[u].y * a2dr));
        red_add_v2((float*)&g_nd2f[sd[u].y], wf * Hs[u].x, wf);
        red_add_v2((float*)&g_nd2r[sd[u].x], wr * Hd[u].y, wr);
    }
}

// ---------------- final combine (2 nodes/thread, vectorized) ----------------
__global__ void k_out(float* __restrict__ out, const float* __restrict__ b2,
                      const float* __restrict__ b2r, int N) {
    int t = blockIdx.x * blockDim.x + threadIdx.x;
    int i = 2 * t;
    if (i >= N) return;
    float bf = __ldg(&b2[0]), br = __ldg(&b2r[0]);
    float4 f = ((const float4*)g_nd2f)[t];   // nd2f[i], nd2f[i+1]
    float4 r = ((const float4*)g_nd2r)[t];
    float o0 = 0.5f * (f.x / (f.y + 1e-16f) + bf + r.x / (r.y + 1e-16f) + br);
    if (i + 1 < N) {
        float o1 = 0.5f * (f.z / (f.w + 1e-16f) + bf + r.z / (r.w + 1e-16f) + br);
        *(float2*)&out[i] = make_float2(o0, o1);
    } else {
        out[i] = o0;
    }
}

extern "C" void kernel_launch(void* const* d_in, const int* in_sizes, int n_in,
                              void* d_out, int out_size) {
    const float* x   = (const float*)d_in[0];
    const void*  ei  = d_in[1];
    const float* W1  = (const float*)d_in[2];
    const float* as1 = (const float*)d_in[3];
    const float* ad1 = (const float*)d_in[4];
    const float* b1  = (const float*)d_in[5];
    const float* W2  = (const float*)d_in[6];
    const float* as2 = (const float*)d_in[7];
    const float* ad2 = (const float*)d_in[8];
    const float* b2  = (const float*)d_in[9];
    const float* W1r  = (const float*)d_in[10];
    const float* as1r = (const float*)d_in[11];
    const float* ad1r = (const float*)d_in[12];
    const float* b1r  = (const float*)d_in[13];
    const float* W2r  = (const float*)d_in[14];
    const float* as2r = (const float*)d_in[15];
    const float* ad2r = (const float*)d_in[16];
    const float* b2r  = (const float*)d_in[17];

    int N = in_sizes[0] / 3;
    int E = in_sizes[1] / 2;

    const int TB = 256;
    int nbN = (N + TB - 1) / TB;
    int nbE = (E + TB * EPT - 1) / (TB * EPT);
    int nb2 = (N + TB * 2 - 1) / (TB * 2);

    k_node1<<<nbN, TB>>>(x, W1, as1, ad1, W1r, as1r, ad1r, N);
    k_edge1<<<nbE, TB>>>(ei, E);
    k_node2<<<nb2, TB>>>(W1, b1, W2, as2, ad2, W1r, b1r, W2r, as2r, ad2r, N);
    k_edge2<<<nbE, TB>>>(as2, ad2, as2r, ad2r, E);
    k_out<<<nb2, TB>>>((float*)d_out, b2, b2r, N);
}

// round 7
// speedup vs baseline: 1.0860x; 1.0860x over previous
#include <cuda_runtime.h>

#define NEG_SLOPE 0.2f
#define MAXN 100000
#define MAXE 3200000
#define EPT 2          // edges per thread in edge passes

static __device__ __forceinline__ float lrelu(float v) {
    return v > 0.f ? v : NEG_SLOPE * v;
}

static __device__ __forceinline__ void red_add_v2(float* addr, float a, float b) {
    asm volatile("red.global.add.v2.f32 [%0], {%1,%2};" :: "l"(addr), "f"(a), "f"(b) : "memory");
}
static __device__ __forceinline__ void red_add_v4(float* addr, float a, float b, float c, float d) {
    asm volatile("red.global.add.v4.f32 [%0], {%1,%2,%3,%4};"
                 :: "l"(addr), "f"(a), "f"(b), "f"(c), "f"(d) : "memory");
}

static __device__ __forceinline__ float dot3(float4 v, float4 c) {
    return v.x * c.x + v.y * c.y + v.z * c.z;
}

// ---------------- scratch (device globals; no runtime allocation) ----------------
__device__ __align__(16) int2 g_sd[MAXE];    // packed (src,dst): written by edge1, read by edge2

// Layer-1: per-node state is x (float4, 1 sector). Scores are linear in x.
__device__ __align__(16) float4 g_X[MAXN];
__device__ float4 g_csf, g_cdf, g_csr, g_cdr;   // W1@as1, W1@ad1, W1r@as1r, W1r@ad1r
// Accumulators: (sum w*x0, w*x1, w*x2, sum w)
__device__ __align__(16) float4 g_accf[MAXN];
__device__ __align__(16) float4 g_accr[MAXN];

// Layer-2: per-node state is (h2f, h2r).
__device__ __align__(16) float2 g_H[MAXN];
__device__ __align__(16) float2 g_nd2f[MAXN];
__device__ __align__(16) float2 g_nd2r[MAXN];

// ---------------- uniform score coefficients (once) ----------------
__global__ void k_coef(const float* __restrict__ W1,  const float* __restrict__ as1,
                       const float* __restrict__ ad1,
                       const float* __restrict__ W1r, const float* __restrict__ as1r,
                       const float* __restrict__ ad1r) {
    if (threadIdx.x != 0) return;
    float csf[3] = {0,0,0}, cdf[3] = {0,0,0}, csr[3] = {0,0,0}, cdr[3] = {0,0,0};
    for (int f = 0; f < 16; f++) {
        for (int k = 0; k < 3; k++) {
            float w  = W1[16 * k + f];
            float wr = W1r[16 * k + f];
            csf[k] += w * as1[f];   cdf[k] += w * ad1[f];
            csr[k] += wr * as1r[f]; cdr[k] += wr * ad1r[f];
        }
    }
    g_csf = make_float4(csf[0], csf[1], csf[2], 0.f);
    g_cdf = make_float4(cdf[0], cdf[1], cdf[2], 0.f);
    g_csr = make_float4(csr[0], csr[1], csr[2], 0.f);
    g_cdr = make_float4(cdr[0], cdr[1], cdr[2], 0.f);
}

// ---------------- layer 1 node prep ----------------
__global__ void k_node1(const float* __restrict__ x, int N) {
    int i = blockIdx.x * blockDim.x + threadIdx.x;
    if (i >= N) return;
    float4 csf = g_csf, cdf = g_cdf, csr = g_csr, cdr = g_cdr;
    float x0 = x[3 * i], x1 = x[3 * i + 1], x2 = x[3 * i + 2];
    float4 X = make_float4(x0, x1, x2, 0.f);

    float ssf = dot3(X, csf), sdf = dot3(X, cdf);
    float ssr = dot3(X, csr), sdr = dot3(X, cdr);

    g_X[i] = X;
    // self-loop contribution
    float wf = __expf(lrelu(ssf + sdf));
    float wr = __expf(lrelu(ssr + sdr));
    g_accf[i] = make_float4(wf * x0, wf * x1, wf * x2, wf);
    g_accr[i] = make_float4(wr * x0, wr * x1, wr * x2, wr);
}

// ---------------- layer 1 edge pass: 2 gathers + 2 REDs per edge ----------------
__global__ void __launch_bounds__(256) k_edge1(const void* __restrict__ ei, int E) {
    // per-block int64-vs-int32 detection: odd 32-bit words of int64 data are
    // all-zero high halves; genuine int32 node ids are ~never 128-in-a-row zero.
    __shared__ int s_is64;
    if (threadIdx.x == 0) s_is64 = 1;
    __syncthreads();
    if (threadIdx.x < 128) {
        if (((const int*)ei)[1 + 2 * threadIdx.x] != 0) s_is64 = 0;
    }
    __syncthreads();
    bool is64 = (s_is64 != 0);

    int t = blockIdx.x * blockDim.x + threadIdx.x;
    int j0 = t * EPT;
    if (j0 >= E) return;
    int n = E - j0; if (n > EPT) n = EPT;

    float4 csf = g_csf, cdf = g_cdf, csr = g_csr, cdr = g_cdr;

    int s[EPT], d[EPT];
    if (is64) {
        const long long* p = (const long long*)ei;
#pragma unroll
        for (int u = 0; u < EPT; u++) if (u < n) { s[u] = (int)p[j0 + u]; d[u] = (int)p[E + j0 + u]; }
    } else {
        const int* p = (const int*)ei;
#pragma unroll
        for (int u = 0; u < EPT; u++) if (u < n) { s[u] = p[j0 + u]; d[u] = p[E + j0 + u]; }
    }
#pragma unroll
    for (int u = 0; u < EPT; u++) if (u < n) g_sd[j0 + u] = make_int2(s[u], d[u]);

    float4 Xs[EPT], Xd[EPT];
#pragma unroll
    for (int u = 0; u < EPT; u++) if (u < n) {
        Xs[u] = g_X[s[u]];
        Xd[u] = g_X[d[u]];
    }
#pragma unroll
    for (int u = 0; u < EPT; u++) if (u < n) {
        // forward edge s->d: exp(lrelu(ssf[s] + sdf[d])) -> accf[d]
        float wf = __expf(lrelu(dot3(Xs[u], csf) + dot3(Xd[u], cdf)));
        // reverse edge d->s: exp(lrelu(ssr[d] + sdr[s])) -> accr[s]
        float wr = __expf(lrelu(dot3(Xd[u], csr) + dot3(Xs[u], cdr)));
        red_add_v4((float*)&g_accf[d[u]], wf * Xs[u].x, wf * Xs[u].y, wf * Xs[u].z, wf);
        red_add_v4((float*)&g_accr[s[u]], wr * Xd[u].x, wr * Xd[u].y, wr * Xd[u].z, wr);
    }
}

// ---------------- layer 2 node prep: 2 nodes/thread, shared weight loads ----------------
__global__ void k_node2(const float* __restrict__ W1, const float* __restrict__ b1,
                        const float* __restrict__ W2,
                        const float* __restrict__ as2, const float* __restrict__ ad2,
                        const float* __restrict__ W1r, const float* __restrict__ b1r,
                        const float* __restrict__ W2r,
                        const float* __restrict__ as2r, const float* __restrict__ ad2r, int N) {
    int t = blockIdx.x * blockDim.x + threadIdx.x;
    int i0 = 2 * t;
    if (i0 >= N) return;
    int cnt = (i0 + 1 < N) ? 2 : 1;

    float nf[2][3], nr[2][3];
#pragma unroll
    for (int v = 0; v < 2; v++) if (v < cnt) {
        float4 af = g_accf[i0 + v];
        float4 ar = g_accr[i0 + v];
        float invf = 1.f / (af.w + 1e-16f);
        float invr = 1.f / (ar.w + 1e-16f);
        nf[v][0] = af.x * invf; nf[v][1] = af.y * invf; nf[v][2] = af.z * invf;
        nr[v][0] = ar.x * invr; nr[v][1] = ar.y * invr; nr[v][2] = ar.z * invr;
    }

    const float4* W1v  = (const float4*)W1;   // [3][4] float4s
    const float4* W1rv = (const float4*)W1r;
    const float4* b1v  = (const float4*)b1;
    const float4* b1rv = (const float4*)b1r;
    const float4* W2v  = (const float4*)W2;
    const float4* W2rv = (const float4*)W2r;

    float h2f[2] = {0.f, 0.f}, h2r[2] = {0.f, 0.f};
#pragma unroll
    for (int q = 0; q < 4; q++) {
        float4 w0 = __ldg(&W1v[q]),  w1 = __ldg(&W1v[4 + q]),  w2 = __ldg(&W1v[8 + q]);
        float4 bb = __ldg(&b1v[q]),  wo = __ldg(&W2v[q]);
        float4 r0 = __ldg(&W1rv[q]), r1 = __ldg(&W1rv[4 + q]), r2 = __ldg(&W1rv[8 + q]);
        float4 br = __ldg(&b1rv[q]), ro = __ldg(&W2rv[q]);
#pragma unroll
        for (int v = 0; v < 2; v++) if (v < cnt) {
            h2f[v] += fmaxf(nf[v][0] * w0.x + nf[v][1] * w1.x + nf[v][2] * w2.x + bb.x, 0.f) * wo.x;
            h2f[v] += fmaxf(nf[v][0] * w0.y + nf[v][1] * w1.y + nf[v][2] * w2.y + bb.y, 0.f) * wo.y;
            h2f[v] += fmaxf(nf[v][0] * w0.z + nf[v][1] * w1.z + nf[v][2] * w2.z + bb.z, 0.f) * wo.z;
            h2f[v] += fmaxf(nf[v][0] * w0.w + nf[v][1] * w1.w + nf[v][2] * w2.w + bb.w, 0.f) * wo.w;
            h2r[v] += fmaxf(nr[v][0] * r0.x + nr[v][1] * r1.x + nr[v][2] * r2.x + br.x, 0.f) * ro.x;
            h2r[v] += fmaxf(nr[v][0] * r0.y + nr[v][1] * r1.y + nr[v][2] * r2.y + br.y, 0.f) * ro.y;
            h2r[v] += fmaxf(nr[v][0] * r0.z + nr[v][1] * r1.z + nr[v][2] * r2.z + br.z, 0.f) * ro.z;
            h2r[v] += fmaxf(nr[v][0] * r0.w + nr[v][1] * r1.w + nr[v][2] * r2.w + br.w, 0.f) * ro.w;
        }
    }

    float sum2f = __ldg(&as2[0]) + __ldg(&ad2[0]);
    float sum2r = __ldg(&as2r[0]) + __ldg(&ad2r[0]);
#pragma unroll
    for (int v = 0; v < 2; v++) if (v < cnt) {
        g_H[i0 + v] = make_float2(h2f[v], h2r[v]);
        float wf = __expf(lrelu(h2f[v] * sum2f));
        float wr = __expf(lrelu(h2r[v] * sum2r));
        g_nd2f[i0 + v] = make_float2(wf * h2f[v], wf);
        g_nd2r[i0 + v] = make_float2(wr * h2r[v], wr);
    }
}

// ---------------- layer 2 edge pass: 2 gathers + 2 REDs per edge ----------------
__global__ void __launch_bounds__(256) k_edge2(const float* __restrict__ as2,
                                               const float* __restrict__ ad2,
                                               const float* __restrict__ as2r,
                                               const float* __restrict__ ad2r, int E) {
    float a2s = __ldg(&as2[0]),  a2d = __ldg(&ad2[0]);
    float a2sr = __ldg(&as2r[0]), a2dr = __ldg(&ad2r[0]);

    int t = blockIdx.x * blockDim.x + threadIdx.x;
    int j0 = t * EPT;
    if (j0 >= E) return;
    int n = E - j0; if (n > EPT) n = EPT;

    int2 sd[EPT];
#pragma unroll
    for (int u = 0; u < EPT; u++) if (u < n) sd[u] = g_sd[j0 + u];

    float2 Hs[EPT], Hd[EPT];
#pragma unroll
    for (int u = 0; u < EPT; u++) if (u < n) {
        Hs[u] = g_H[sd[u].x];
        Hd[u] = g_H[sd[u].y];
    }
#pragma unroll
    for (int u = 0; u < EPT; u++) if (u < n) {
        // forward s->d: score = h2f[s]*as2 + h2f[d]*ad2
        float wf = __expf(lrelu(Hs[u].x * a2s + Hd[u].x * a2d));
        // reverse d->s: score = h2r[d]*as2r + h2r[s]*ad2r
        float wr = __expf(lrelu(Hd[u].y * a2sr + Hs[u].y * a2dr));
        red_add_v2((float*)&g_nd2f[sd[u].y], wf * Hs[u].x, wf);
        red_add_v2((float*)&g_nd2r[sd[u].x], wr * Hd[u].y, wr);
    }
}

// ---------------- final combine (2 nodes/thread, vectorized) ----------------
__global__ void k_out(float* __restrict__ out, const float* __restrict__ b2,
                      const float* __restrict__ b2r, int N) {
    int t = blockIdx.x * blockDim.x + threadIdx.x;
    int i = 2 * t;
    if (i >= N) return;
    float bf = __ldg(&b2[0]), br = __ldg(&b2r[0]);
    float4 f = ((const float4*)g_nd2f)[t];   // nd2f[i], nd2f[i+1]
    float4 r = ((const float4*)g_nd2r)[t];
    float o0 = 0.5f * (f.x / (f.y + 1e-16f) + bf + r.x / (r.y + 1e-16f) + br);
    if (i + 1 < N) {
        float o1 = 0.5f * (f.z / (f.w + 1e-16f) + bf + r.z / (r.w + 1e-16f) + br);
        *(float2*)&out[i] = make_float2(o0, o1);
    } else {
        out[i] = o0;
    }
}

extern "C" void kernel_launch(void* const* d_in, const int* in_sizes, int n_in,
                              void* d_out, int out_size) {
    const float* x   = (const float*)d_in[0];
    const void*  ei  = d_in[1];
    const float* W1  = (const float*)d_in[2];
    const float* as1 = (const float*)d_in[3];
    const float* ad1 = (const float*)d_in[4];
    const float* b1  = (const float*)d_in[5];
    const float* W2  = (const float*)d_in[6];
    const float* as2 = (const float*)d_in[7];
    const float* ad2 = (const float*)d_in[8];
    const float* b2  = (const float*)d_in[9];
    const float* W1r  = (const float*)d_in[10];
    const float* as1r = (const float*)d_in[11];
    const float* ad1r = (const float*)d_in[12];
    const float* b1r  = (const float*)d_in[13];
    const float* W2r  = (const float*)d_in[14];
    const float* as2r = (const float*)d_in[15];
    const float* ad2r = (const float*)d_in[16];
    const float* b2r  = (const float*)d_in[17];

    int N = in_sizes[0] / 3;
    int E = in_sizes[1] / 2;

    const int TB = 256;
    int nbN = (N + TB - 1) / TB;
    int nbE = (E + TB * EPT - 1) / (TB * EPT);
    int nb2 = (N + TB * 2 - 1) / (TB * 2);

    k_coef<<<1, 32>>>(W1, as1, ad1, W1r, as1r, ad1r);
    k_node1<<<nbN, TB>>>(x, N);
    k_edge1<<<nbE, TB>>>(ei, E);
    k_node2<<<nb2, TB>>>(W1, b1, W2, as2, ad2, W1r, b1r, W2r, as2r, ad2r, N);
    k_edge2<<<nbE, TB>>>(as2, ad2, as2r, ad2r, E);
    k_out<<<nb2, TB>>>((float*)d_out, b2, b2r, N);
}